// round 4
// baseline (speedup 1.0000x reference)
#include <cuda_runtime.h>

// Problem constants
#define BATCH   64
#define TLEN    8192
#define DECL    64
#define NWIN    (TLEN - DECL)      // 8128
#define CHUNKS  8
#define WPC     (NWIN / CHUNKS)    // 1016 windows per chunk
#define TPB     256                // 8 warps: 128 window-threads x 2 j-halves
#define NWT     128                // window-threads (lane halves) per block
#define WPT     8                  // windows per window-thread
#define JH      32                 // j-steps per half

// smem x tile: max read index l0max(=1016) + 32(off) + 31 + 8 = 1087
#define XTILE   1088
#define XTILEP  (XTILE + XTILE / 8)   // padded (i -> i + i/8): stride-8 ring refill -> stride 9, conflict-free

// Cross-block combine scratch (zero-init; kernel restores zeros after use so
// every graph replay sees identical initial state).
__device__ unsigned long long g_best[BATCH]; // max over ~key
__device__ unsigned int       g_cnt[BATCH];

__device__ __forceinline__ int padi(int i) { return i + (i >> 3); }

__global__ __launch_bounds__(TPB, 4)
void match_kernel(const float* __restrict__ X_in,
                  const float* __restrict__ X_out,
                  float* __restrict__ out)
{
    __shared__ float xs[XTILEP];
    __shared__ float ys[DECL];
    __shared__ unsigned long long red[TPB / 32];
    __shared__ int lastFlag;

    const int c    = blockIdx.x;    // chunk
    const int b    = blockIdx.y;    // batch
    const int tid  = threadIdx.x;
    const int lane = tid & 31;
    const int warp = tid >> 5;

    const float* xb = X_in + (size_t)b * TLEN;
    const int base  = c * WPC;      // first window of this chunk

    // Tile load (scalar, guarded only at the true tail) + y load
    for (int i = tid; i < XTILE; i += TPB) {
        int g = base + i;
        xs[padi(i)] = (g < TLEN) ? xb[g] : 0.0f;
    }
    if (tid < DECL) ys[tid] = X_out[b * DECL + tid];
    __syncthreads();

    // Lane-half decomposition: lanes 0-15 -> j in [0,32), lanes 16-31 -> j in [32,64)
    const int lane16 = lane & 15;
    const int h      = lane >> 4;
    const int wt     = warp * 16 + lane16;  // window-thread id, 0..127
    const int l0     = wt * WPT;            // first local window
    const int off    = h * JH;              // j offset for this half

    // Sliding 8-register ring over x[l0+off ...]:
    // ring holds x[l0+off+j .. l0+off+j+7]; element (l0+off+j+w) at slot (j+w)&7.
    float ring[8];
    #pragma unroll
    for (int w = 0; w < 8; ++w) ring[w] = xs[padi(l0 + off + w)];

    float acc0 = 0.f, acc1 = 0.f, acc2 = 0.f, acc3 = 0.f;
    float acc4 = 0.f, acc5 = 0.f, acc6 = 0.f, acc7 = 0.f;
    float sxp  = 0.f;               // partial sum x^2 for window w=0 over this half's j-range

    #pragma unroll
    for (int j = 0; j < JH; ++j) {
        float yj = ys[off + j];
        acc0 = fmaf(ring[(j + 0) & 7], yj, acc0);
        acc1 = fmaf(ring[(j + 1) & 7], yj, acc1);
        acc2 = fmaf(ring[(j + 2) & 7], yj, acc2);
        acc3 = fmaf(ring[(j + 3) & 7], yj, acc3);
        acc4 = fmaf(ring[(j + 4) & 7], yj, acc4);
        acc5 = fmaf(ring[(j + 5) & 7], yj, acc5);
        acc6 = fmaf(ring[(j + 6) & 7], yj, acc6);
        acc7 = fmaf(ring[(j + 7) & 7], yj, acc7);
        float v = ring[j & 7];      // leaving element: x[l0+off+j]
        sxp = fmaf(v, v, sxp);
        ring[j & 7] = xs[padi(l0 + off + j + 8)];
    }
    // After loop: ring[i] = x[l0 + off + 32 + i], i = 0..7  ((32+i)&7 == i).

    // Partial score P_h[w] = sum_{j in half} x[l0+w+j]^2 - 2*sum x[l0+w+j]*y[j]
    float acc[8] = {acc0, acc1, acc2, acc3, acc4, acc5, acc6, acc7};
    float part[8];
    part[0] = fmaf(-2.0f, acc[0], sxp);
    float s = sxp;
    #pragma unroll
    for (int w = 1; w < 8; ++w) {
        float xin  = ring[w - 1];                 // x[l0 + w - 1 + off + 32]
        float xout = xs[padi(l0 + off + w - 1)];  // x[l0 + w - 1 + off]
        s = fmaf(xin, xin, s);
        s = fmaf(-xout, xout, s);
        part[w] = fmaf(-2.0f, acc[w], s);
    }

    // Combine halves: partner lane (lane ^ 16) holds the other j-half of the
    // SAME windows. Both halves end with identical full scores (dup keys are
    // harmless under max-reduction).
    float score[8];
    #pragma unroll
    for (int w = 0; w < 8; ++w)
        score[w] = part[w] + __shfl_xor_sync(0xFFFFFFFFu, part[w], 16);

    // Thread-local argmin, first-index tie-break, monotonic packed key.
    unsigned long long bestik = 0ULL;       // max over ~key
    #pragma unroll
    for (int w = 0; w < 8; ++w) {
        int lw    = l0 + w;
        int gidx  = base + lw;
        bool valid = (lw < WPC);
        float sc  = valid ? score[w] : __int_as_float(0x7F800000); // +inf
        unsigned u = __float_as_uint(sc);
        unsigned m = u ^ ((unsigned)((int)u >> 31) | 0x80000000u); // monotonic map
        unsigned long long key = ((unsigned long long)m << 32) | (unsigned)gidx;
        unsigned long long ik  = ~key;      // max(ik) == min(key); tie -> smaller idx
        bestik = bestik > ik ? bestik : ik;
    }

    // Warp reduce (max over ~key)
    #pragma unroll
    for (int o = 16; o; o >>= 1) {
        unsigned long long v = __shfl_down_sync(0xFFFFFFFFu, bestik, o);
        bestik = bestik > v ? bestik : v;
    }
    if (lane == 0) red[warp] = bestik;
    __syncthreads();

    if (tid == 0) {
        unsigned long long k = red[0];
        #pragma unroll
        for (int i = 1; i < TPB / 32; ++i) k = k > red[i] ? k : red[i];
        atomicMax(&g_best[b], k);
        __threadfence();
        unsigned prev = atomicAdd(&g_cnt[b], 1u);
        lastFlag = (prev == CHUNKS - 1) ? 1 : 0;
    }
    __syncthreads();

    // Last block for this batch gathers output and restores scratch.
    if (lastFlag) {
        unsigned long long k = atomicMax(&g_best[b], 0ULL); // atomic read
        int start = (int)((~k) & 0xFFFFFFFFull);
        if (tid < DECL) out[b * DECL + tid] = xb[start + tid];
        __syncthreads();
        if (tid == 0) { g_best[b] = 0ULL; g_cnt[b] = 0u; }
    }
}

extern "C" void kernel_launch(void* const* d_in, const int* in_sizes, int n_in,
                              void* d_out, int out_size)
{
    // inputs: 0=feats_in (unused), 1=X_in, 2=feats_out (unused), 3=X_out
    const float* X_in  = (const float*)d_in[1];
    const float* X_out = (const float*)d_in[3];
    float* out = (float*)d_out;

    dim3 grid(CHUNKS, BATCH);
    match_kernel<<<grid, TPB>>>(X_in, X_out, out);
}

// round 5
// speedup vs baseline: 1.4124x; 1.4124x over previous
#include <cuda_runtime.h>

// Problem constants
#define BATCH   64
#define TLEN    8192
#define DECL    64
#define NWIN    (TLEN - DECL)      // 8128
#define CHUNKS  8
#define WPC     (NWIN / CHUNKS)    // 1016 windows per chunk
#define TPB     128
#define WPT     8                  // 128*8 = 1024 >= 1016

// smem x tile: max local read index = 1016 + 71 = 1087
#define XTILE   1088
#define XTILEP  (XTILE + XTILE / 8)   // pad i -> i + i/8: stride-8 refill -> stride 9, conflict-free

// Cross-block combine scratch (zero-init; kernel restores zeros after use so
// every graph replay sees identical initial state).
__device__ unsigned long long g_best[BATCH]; // max over ~key
__device__ unsigned int       g_cnt[BATCH];

__device__ __forceinline__ int padi(int i) { return i + (i >> 3); }

union F2U { float2 f; unsigned long long u; };

// Packed dual FMA: d = a*b + d (per 32-bit lane). Only reachable via PTX.
__device__ __forceinline__ void ffma2(F2U& d, const F2U& a, const F2U& b) {
    asm("fma.rn.f32x2 %0, %1, %2, %0;" : "+l"(d.u) : "l"(a.u), "l"(b.u));
}

__global__ __launch_bounds__(TPB, 4)
void match_kernel(const float* __restrict__ X_in,
                  const float* __restrict__ X_out,
                  float* __restrict__ out)
{
    __shared__ float  xs[XTILEP];
    __shared__ float2 ys2[DECL];               // (y_j, y_j) pairs for LDS.64 broadcast
    __shared__ unsigned long long red[TPB / 32];
    __shared__ int lastFlag;

    const int c   = blockIdx.x;     // chunk
    const int b   = blockIdx.y;     // batch
    const int tid = threadIdx.x;

    const float* xb = X_in + (size_t)b * TLEN;
    const int base  = c * WPC;

    // y first (overlaps with x tile LDGs)
    if (tid < DECL) {
        float v = X_out[b * DECL + tid];
        ys2[tid] = make_float2(v, v);
    }
    for (int i = tid; i < XTILE; i += TPB) {
        int g = base + i;
        xs[padi(i)] = (g < TLEN) ? xb[g] : 0.0f;
    }
    __syncthreads();

    const int l0 = tid * WPT;

    // Packed sliding ring: at step j, pr[(j+k)&3] = (x[l0+j+k], x[l0+j+k+4]).
    F2U pr[4];
    #pragma unroll
    for (int k = 0; k < 4; ++k) {
        pr[k].f.x = xs[padi(l0 + k)];
        pr[k].f.y = xs[padi(l0 + k + 4)];
    }

    F2U pacc[4];                    // pacc[k] = (acc_k, acc_{k+4})
    #pragma unroll
    for (int k = 0; k < 4; ++k) { pacc[k].f.x = 0.f; pacc[k].f.y = 0.f; }
    float sx2 = 0.f;                // sum x^2 for window w=0

    #pragma unroll
    for (int j = 0; j < DECL; ++j) {
        F2U yy; yy.f = ys2[j];      // broadcast pair
        ffma2(pacc[0], pr[(j + 0) & 3], yy);
        ffma2(pacc[1], pr[(j + 1) & 3], yy);
        ffma2(pacc[2], pr[(j + 2) & 3], yy);
        ffma2(pacc[3], pr[(j + 3) & 3], yy);
        float vlo = pr[j & 3].f.x;          // leaving element x[l0+j]
        sx2 = fmaf(vlo, vlo, sx2);
        float nh = xs[padi(l0 + j + 8)];
        pr[j & 3].f.x = pr[j & 3].f.y;      // pair shift: (x[l0+j+4], x[l0+j+8])
        pr[j & 3].f.y = nh;
    }
    // After loop: pr[k] = (x[l0+64+k], x[l0+68+k]), k=0..3.

    float acc[8];
    #pragma unroll
    for (int k = 0; k < 4; ++k) { acc[k] = pacc[k].f.x; acc[k + 4] = pacc[k].f.y; }

    float score[8];
    score[0] = fmaf(-2.0f, acc[0], sx2);
    float s = sx2;
    #pragma unroll
    for (int w = 1; w < 8; ++w) {
        float xin  = (w <= 4) ? pr[w - 1].f.x : pr[w - 5].f.y;  // x[l0+w+63]
        float xout = xs[padi(l0 + w - 1)];                       // x[l0+w-1]
        s = fmaf(xin, xin, s);
        s = fmaf(-xout, xout, s);
        score[w] = fmaf(-2.0f, acc[w], s);
    }

    // Thread-local argmin, first-index tie-break, monotonic packed key.
    unsigned long long bestik = 0ULL;       // max over ~key
    #pragma unroll
    for (int w = 0; w < 8; ++w) {
        int lw    = l0 + w;
        int gidx  = base + lw;
        bool valid = (lw < WPC);
        float sc  = valid ? score[w] : __int_as_float(0x7F800000); // +inf
        unsigned u = __float_as_uint(sc);
        unsigned m = u ^ ((unsigned)((int)u >> 31) | 0x80000000u); // monotonic map
        unsigned long long key = ((unsigned long long)m << 32) | (unsigned)gidx;
        unsigned long long ik  = ~key;      // max(ik) == min(key); tie -> smaller idx
        bestik = bestik > ik ? bestik : ik;
    }

    // Warp reduce (max over ~key)
    #pragma unroll
    for (int o = 16; o; o >>= 1) {
        unsigned long long v = __shfl_down_sync(0xFFFFFFFFu, bestik, o);
        bestik = bestik > v ? bestik : v;
    }
    if ((tid & 31) == 0) red[tid >> 5] = bestik;
    __syncthreads();

    if (tid == 0) {
        unsigned long long k = red[0];
        #pragma unroll
        for (int i = 1; i < TPB / 32; ++i) k = k > red[i] ? k : red[i];
        atomicMax(&g_best[b], k);
        __threadfence();
        unsigned prev = atomicAdd(&g_cnt[b], 1u);
        lastFlag = (prev == CHUNKS - 1) ? 1 : 0;
    }
    __syncthreads();

    // Last block for this batch gathers output and restores scratch.
    if (lastFlag) {
        unsigned long long k = atomicMax(&g_best[b], 0ULL); // atomic read
        int start = (int)((~k) & 0xFFFFFFFFull);
        if (tid < DECL) out[b * DECL + tid] = xb[start + tid];
        __syncthreads();
        if (tid == 0) { g_best[b] = 0ULL; g_cnt[b] = 0u; }
    }
}

extern "C" void kernel_launch(void* const* d_in, const int* in_sizes, int n_in,
                              void* d_out, int out_size)
{
    // inputs: 0=feats_in (unused), 1=X_in, 2=feats_out (unused), 3=X_out
    const float* X_in  = (const float*)d_in[1];
    const float* X_out = (const float*)d_in[3];
    float* out = (float*)d_out;

    dim3 grid(CHUNKS, BATCH);
    match_kernel<<<grid, TPB>>>(X_in, X_out, out);
}